// round 1
// baseline (speedup 1.0000x reference)
#include <cuda_runtime.h>
#include <math.h>

// ---------------------------------------------------------------------------
// QuickPatternMatchingLoss — algebraic reduction of the reference:
//
//   out[b] = log( (1/ls) * sum_{l: mask} sum_o ss_hmm[o,l] *
//                 softmax_o( W[:, :20] . x[b,1:,l] + slog[:,l] ) )
//   slog[o,l] = b[o] + sum_h W[o,20+h] * seq_hmm[h,l]          (batch-invariant)
//   mask[b,l] = ( max_{c>=1} x[b,c,l] > x[b,0,l] )             (argmax != 0)
//
// The _pack permutation in the reference cancels exactly (hmm and weights are
// permuted by the same dest), so the kernel is a pure streaming reduction
// over x: 176 MB read once -> HBM-bound.
// ---------------------------------------------------------------------------

#define MAX_L 2048
__device__ float g_slog[3 * MAX_L];   // batch-invariant logits (prologue output)

// ---- prologue: slog[o,l] = b[o] + sum_h W[o,20+h] * seq_hmm[h,l] ----------
__global__ void slog_kernel(const float* __restrict__ seq_hmm,
                            const float* __restrict__ W,
                            const float* __restrict__ bvec,
                            int L, int H, int wstride)
{
    int l = blockIdx.x * blockDim.x + threadIdx.x;
    if (l >= L) return;
    float s0 = bvec[0], s1 = bvec[1], s2 = bvec[2];
    for (int h = 0; h < H; ++h) {
        float v = seq_hmm[h * L + l];
        s0 = fmaf(W[0 * wstride + 20 + h], v, s0);
        s1 = fmaf(W[1 * wstride + 20 + h], v, s1);
        s2 = fmaf(W[2 * wstride + 20 + h], v, s2);
    }
    g_slog[0 * L + l] = s0;
    g_slog[1 * L + l] = s1;
    g_slog[2 * L + l] = s2;
}

// ---- main kernel: one CTA per batch row, float4 (4 columns per thread) ----
// NC > 0: compile-time channel count (fully unrolled mainloop, MLP = NC).
template <int NC>
__global__ void __launch_bounds__(128)
qpml_kernel(const float* __restrict__ x,
            const float* __restrict__ ss_hmm,
            const float* __restrict__ W,
            float* __restrict__ out,
            int L, int nc_rt, int wstride)
{
    const int b = blockIdx.x;
    const int t = threadIdx.x;
    const int C = (NC > 0) ? NC : nc_rt;

    // Stage W[:, :20] (the x-channel weights) into smem.
    __shared__ float sW0[20], sW1[20], sW2[20];
    if (t < 20) {
        sW0[t] = W[0 * wstride + t];
        sW1[t] = W[1 * wstride + t];
        sW2[t] = W[2 * wstride + t];
    }
    __syncthreads();

    const float4* xb = (const float4*)(x + (size_t)b * (size_t)C * (size_t)L);
    const int Lv = L >> 2;   // float4 columns

    float contrib = 0.f, cnt = 0.f;

    for (int i = t; i < Lv; i += 128) {
        // channel 0 (gap channel)
        float4 v0 = __ldg(&xb[i]);
        float x0[4] = {v0.x, v0.y, v0.z, v0.w};
        float mx[4] = {-INFINITY, -INFINITY, -INFINITY, -INFINITY};
        float a0[4] = {0.f, 0.f, 0.f, 0.f};
        float a1[4] = {0.f, 0.f, 0.f, 0.f};
        float a2[4] = {0.f, 0.f, 0.f, 0.f};

        #pragma unroll
        for (int c = 1; c < C; ++c) {
            float4 v = __ldg(&xb[c * Lv + i]);
            float vv[4] = {v.x, v.y, v.z, v.w};
            float w0 = sW0[c - 1], w1 = sW1[c - 1], w2 = sW2[c - 1];
            #pragma unroll
            for (int j = 0; j < 4; ++j) {
                mx[j] = fmaxf(mx[j], vv[j]);
                a0[j] = fmaf(w0, vv[j], a0[j]);
                a1[j] = fmaf(w1, vv[j], a1[j]);
                a2[j] = fmaf(w2, vv[j], a2[j]);
            }
        }

        // batch-invariant logits + weights (L2-resident: 6 KB each)
        float4 s0 = *(const float4*)&g_slog[0 * L + 4 * i];
        float4 s1 = *(const float4*)&g_slog[1 * L + 4 * i];
        float4 s2 = *(const float4*)&g_slog[2 * L + 4 * i];
        float4 h0 = __ldg((const float4*)&ss_hmm[0 * L + 4 * i]);
        float4 h1 = __ldg((const float4*)&ss_hmm[1 * L + 4 * i]);
        float4 h2 = __ldg((const float4*)&ss_hmm[2 * L + 4 * i]);
        float sa0[4] = {s0.x, s0.y, s0.z, s0.w};
        float sa1[4] = {s1.x, s1.y, s1.z, s1.w};
        float sa2[4] = {s2.x, s2.y, s2.z, s2.w};
        float ha0[4] = {h0.x, h0.y, h0.z, h0.w};
        float ha1[4] = {h1.x, h1.y, h1.z, h1.w};
        float ha2[4] = {h2.x, h2.y, h2.z, h2.w};

        #pragma unroll
        for (int j = 0; j < 4; ++j) {
            float e0 = __expf(a0[j] + sa0[j]);
            float e1 = __expf(a1[j] + sa1[j]);
            float e2 = __expf(a2[j] + sa2[j]);
            float num = ha0[j] * e0 + ha1[j] * e1 + ha2[j] * e2;
            float den = e0 + e1 + e2;
            if (mx[j] > x0[j]) {         // non-gap position
                contrib += num / den;
                cnt += 1.f;
            }
        }
    }

    // ---- block reduction (128 threads = 4 warps) ----
    #pragma unroll
    for (int off = 16; off > 0; off >>= 1) {
        contrib += __shfl_down_sync(0xffffffffu, contrib, off);
        cnt     += __shfl_down_sync(0xffffffffu, cnt, off);
    }
    __shared__ float rs[2][4];
    if ((t & 31) == 0) { rs[0][t >> 5] = contrib; rs[1][t >> 5] = cnt; }
    __syncthreads();
    if (t == 0) {
        float s = rs[0][0] + rs[0][1] + rs[0][2] + rs[0][3];
        float c = rs[1][0] + rs[1][1] + rs[1][2] + rs[1][3];
        out[b] = logf(s / c);
    }
}

// ---- scalar fallback for odd shapes (L % 4 != 0) --------------------------
__global__ void qpml_kernel_scalar(const float* __restrict__ x,
                                   const float* __restrict__ ss_hmm,
                                   const float* __restrict__ W,
                                   float* __restrict__ out,
                                   int L, int C, int wstride)
{
    const int b = blockIdx.x;
    const int t = threadIdx.x;
    const float* xb = x + (size_t)b * (size_t)C * (size_t)L;

    float contrib = 0.f, cnt = 0.f;
    for (int l = t; l < L; l += blockDim.x) {
        float x0 = xb[l];
        float mx = -INFINITY;
        float a0 = 0.f, a1 = 0.f, a2 = 0.f;
        for (int c = 1; c < C; ++c) {
            float v = xb[c * L + l];
            mx = fmaxf(mx, v);
            a0 = fmaf(W[0 * wstride + c - 1], v, a0);
            a1 = fmaf(W[1 * wstride + c - 1], v, a1);
            a2 = fmaf(W[2 * wstride + c - 1], v, a2);
        }
        float e0 = __expf(a0 + g_slog[0 * L + l]);
        float e1 = __expf(a1 + g_slog[1 * L + l]);
        float e2 = __expf(a2 + g_slog[2 * L + l]);
        float num = ss_hmm[0 * L + l] * e0 + ss_hmm[1 * L + l] * e1
                  + ss_hmm[2 * L + l] * e2;
        if (mx > x0) { contrib += num / (e0 + e1 + e2); cnt += 1.f; }
    }
    #pragma unroll
    for (int off = 16; off > 0; off >>= 1) {
        contrib += __shfl_down_sync(0xffffffffu, contrib, off);
        cnt     += __shfl_down_sync(0xffffffffu, cnt, off);
    }
    __shared__ float rs[2][32];
    int nw = (blockDim.x + 31) >> 5;
    if ((t & 31) == 0) { rs[0][t >> 5] = contrib; rs[1][t >> 5] = cnt; }
    __syncthreads();
    if (t == 0) {
        float s = 0.f, c = 0.f;
        for (int w = 0; w < nw; ++w) { s += rs[0][w]; c += rs[1][w]; }
        out[b] = logf(s / c);
    }
}

extern "C" void kernel_launch(void* const* d_in, const int* in_sizes, int n_in,
                              void* d_out, int out_size)
{
    const float* x       = (const float*)d_in[0];   // [B, 21, L]
    const float* seq_hmm = (const float*)d_in[1];   // [H, L]
    const float* ss_hmm  = (const float*)d_in[2];   // [3, L]
    const float* W       = (const float*)d_in[3];   // [3, 20+H]
    const float* bvec    = (const float*)d_in[4];   // [3]
    float* out = (float*)d_out;

    const int B       = out_size;                   // 4096
    const int L       = in_sizes[2] / 3;            // 512
    const int H       = in_sizes[1] / L;            // 30
    const int C       = in_sizes[0] / (B * L);      // 21
    const int wstride = in_sizes[3] / 3;            // 20 + H = 50

    slog_kernel<<<(L + 127) / 128, 128>>>(seq_hmm, W, bvec, L, H, wstride);

    if ((L & 3) == 0) {
        if (C == 21)
            qpml_kernel<21><<<B, 128>>>(x, ss_hmm, W, out, L, C, wstride);
        else
            qpml_kernel<0><<<B, 128>>>(x, ss_hmm, W, out, L, C, wstride);
    } else {
        qpml_kernel_scalar<<<B, 128>>>(x, ss_hmm, W, out, L, C, wstride);
    }
}